// round 12
// baseline (speedup 1.0000x reference)
#include <cuda_runtime.h>
#include <cuda_bf16.h>
#include <math.h>
#include <stdint.h>

#define D_MODEL 512
#define D_FF    2048
#define GKN     8
#define NTOK    4096

// K-concat layouts:
//  layer1 activations: [bases(4096) | Sh(512) | Sh(512) | Sl(512)]  strideK=5632
//  layer1 weights:     [Ws  (4096)  | Wbh(512)| Wbl(512)| Wbh(512)]
//  layer2 activations: [bases(16384)| Sh(2048)| Sh(2048)| Sl(2048)] strideK=22528
#define K1P (D_MODEL * GKN + 3 * D_MODEL)   // 5632
#define K2P (D_FF * GKN + 3 * D_FF)         // 22528

__device__ __nv_bfloat16 g_A1[(size_t)NTOK * K1P];
__device__ __nv_bfloat16 g_A2[(size_t)NTOK * K2P];
__device__ __nv_bfloat16 g_W1[(size_t)D_FF * K1P];
__device__ __nv_bfloat16 g_W2[(size_t)D_MODEL * K2P];

// ---------------------------------------------------------------------------
// PTX helpers (arch-agnostic on .target sm_103)
// ---------------------------------------------------------------------------
__device__ __forceinline__ uint32_t cvta_smem(const void* p) {
    uint32_t a;
    asm("{ .reg .u64 t; cvta.to.shared.u64 t, %1; cvt.u32.u64 %0, t; }" : "=r"(a) : "l"(p));
    return a;
}
__device__ __forceinline__ void cp16(uint32_t s, const void* g) {
    asm volatile("cp.async.cg.shared.global [%0], [%1], 16;" :: "r"(s), "l"(g));
}
__device__ __forceinline__ void cp_commit() {
    asm volatile("cp.async.commit_group;" ::: "memory");
}
template <int N>
__device__ __forceinline__ void cp_wait() {
    asm volatile("cp.async.wait_group %0;" :: "n"(N) : "memory");
}
__device__ __forceinline__ void ldmx4(uint32_t* r, uint32_t a) {
    asm volatile("ldmatrix.sync.aligned.m8n8.x4.shared.b16 {%0,%1,%2,%3}, [%4];"
                 : "=r"(r[0]), "=r"(r[1]), "=r"(r[2]), "=r"(r[3]) : "r"(a));
}
__device__ __forceinline__ void mma16816(float* d, const uint32_t* a, uint32_t b0, uint32_t b1) {
    asm volatile(
        "mma.sync.aligned.m16n8k16.row.col.f32.bf16.bf16.f32 "
        "{%0,%1,%2,%3}, {%4,%5,%6,%7}, {%8,%9}, {%0,%1,%2,%3};"
        : "+f"(d[0]), "+f"(d[1]), "+f"(d[2]), "+f"(d[3])
        : "r"(a[0]), "r"(a[1]), "r"(a[2]), "r"(a[3]), "r"(b0), "r"(b1));
}

// ---------------------------------------------------------------------------
// Closed-form uniform cubic B-spline expansion (cardinal N3 translates).
// ---------------------------------------------------------------------------
__device__ __forceinline__ void expand_one(float v, float t0, float ih,
                                           __nv_bfloat16& sh, __nv_bfloat16& sl,
                                           uint4& pk) {
    float s = v * __fdividef(1.0f, 1.0f + __expf(-v));
    sh = __float2bfloat16(s);
    sl = __float2bfloat16(s - __bfloat162float(sh));

    float u = (v - t0) * ih;
    float jf = floorf(u);
    int j0 = (int)jf;
    float w = u - jf;
    float w2 = w * w, w3 = w2 * w;
    const float k6 = 1.0f / 6.0f;
    float c3 = w3 * k6;                                        // q = j0
    float c2 = k6 * (1.0f + 3.0f * w + 3.0f * w2 - 3.0f * w3); // q = j0-1
    float c1 = k6 * (4.0f - 6.0f * w2 + 3.0f * w3);            // q = j0-2
    float c0 = k6 * (1.0f - 3.0f * w + 3.0f * w2 - w3);        // q = j0-3

    float bq[8];
#pragma unroll
    for (int q = 0; q < 8; q++) {
        int d = j0 - q;
        float val = 0.0f;
        val = (d == 0) ? c3 : val;
        val = (d == 1) ? c2 : val;
        val = (d == 2) ? c1 : val;
        val = (d == 3) ? c0 : val;
        bq[q] = val;
    }

    __nv_bfloat162 p0 = __floats2bfloat162_rn(bq[0], bq[1]);
    __nv_bfloat162 p1 = __floats2bfloat162_rn(bq[2], bq[3]);
    __nv_bfloat162 p2 = __floats2bfloat162_rn(bq[4], bq[5]);
    __nv_bfloat162 p3 = __floats2bfloat162_rn(bq[6], bq[7]);
    pk.x = *(uint32_t*)&p0; pk.y = *(uint32_t*)&p1;
    pk.z = *(uint32_t*)&p2; pk.w = *(uint32_t*)&p3;
}

// ---------------------------------------------------------------------------
// Per-element job bodies (prep)
// ---------------------------------------------------------------------------
__device__ __forceinline__ void do_expand(const float* __restrict__ x,
                                          float t0, float ih,
                                          __nv_bfloat16* __restrict__ pA,
                                          int idx, int in_log2, int strideK) {
    const int IN = 1 << in_log2;
    const int row = idx >> in_log2;
    const int i = idx & (IN - 1);

    __nv_bfloat16 sh, sl;
    uint4 pk;
    expand_one(x[idx], t0, ih, sh, sl, pk);

    __nv_bfloat16* rowp = pA + (size_t)row * strideK;
    *(uint4*)(rowp + i * 8) = pk;
    const int off = IN * 8;
    rowp[off + i]          = sh;
    rowp[off + IN + i]     = sh;
    rowp[off + 2 * IN + i] = sl;
}

__device__ __forceinline__ void do_pack_w(const float* __restrict__ wb,
                                          const float* __restrict__ ws,
                                          __nv_bfloat16* __restrict__ pW,
                                          int idx, int in_log2, int strideK) {
    const int IN = 1 << in_log2;
    const int o = idx >> in_log2;
    const int i = idx & (IN - 1);

    float base = wb[idx];
    __nv_bfloat16 hi = __float2bfloat16(base);
    __nv_bfloat16 lo = __float2bfloat16(base - __bfloat162float(hi));

    float4 s0 = ((const float4*)ws)[idx * 2];
    float4 s1 = ((const float4*)ws)[idx * 2 + 1];
    __nv_bfloat162 p0 = __floats2bfloat162_rn(s0.x, s0.y);
    __nv_bfloat162 p1 = __floats2bfloat162_rn(s0.z, s0.w);
    __nv_bfloat162 p2 = __floats2bfloat162_rn(s1.x, s1.y);
    __nv_bfloat162 p3 = __floats2bfloat162_rn(s1.z, s1.w);
    uint4 pk;
    pk.x = *(uint32_t*)&p0; pk.y = *(uint32_t*)&p1;
    pk.z = *(uint32_t*)&p2; pk.w = *(uint32_t*)&p3;

    __nv_bfloat16* rowp = pW + (size_t)o * strideK;
    *(uint4*)(rowp + i * 8) = pk;
    const int off = IN * 8;
    rowp[off + i]          = hi;
    rowp[off + IN + i]     = lo;
    rowp[off + 2 * IN + i] = hi;
}

// ---------------------------------------------------------------------------
// Fused preprocessing: pack W1, pack W2, expand layer-1 input — one launch.
// ---------------------------------------------------------------------------
#define NB1 (D_FF * D_MODEL / 256)           // 4096
#define NB2 (D_MODEL * D_FF / 256)           // 4096
#define NB3 (NTOK * D_MODEL / 256)           // 8192

__global__ void __launch_bounds__(256)
prep_kernel(const float* __restrict__ x, const float* __restrict__ grid,
            const float* __restrict__ w1b, const float* __restrict__ w1s,
            const float* __restrict__ w2b, const float* __restrict__ w2s,
            __nv_bfloat16* __restrict__ W1, __nv_bfloat16* __restrict__ W2,
            __nv_bfloat16* __restrict__ A1) {
    const int b = blockIdx.x;
    if (b < NB1) {
        int idx = b * 256 + threadIdx.x;
        do_pack_w(w1b, w1s, W1, idx, 9, K1P);
    } else if (b < NB1 + NB2) {
        int idx = (b - NB1) * 256 + threadIdx.x;
        do_pack_w(w2b, w2s, W2, idx, 11, K2P);
    } else {
        int idx = (b - NB1 - NB2) * 256 + threadIdx.x;
        const float t0 = __ldg(grid);
        const float ih = __fdividef(1.0f, __ldg(grid + 1) - t0);
        do_expand(x, t0, ih, A1, idx, 9, K1P);
    }
}

// ---------------------------------------------------------------------------
// bf16 mma.sync GEMM: C(M,Nout) = A(M,K) * B(Nout,K)^T, fp32 accumulate.
// 4 warps (2x2), warp tile (MI*16) x (NI*8). BK=64, 3-stage cp.async,
// one __syncthreads per K-iter, fragment double-buffering.
// KAN=true (gemm1 only, BM=128): fused epilogue — stage fp32 acc (=h) through
// SMEM, then each thread expands one token-row into packed A2 (no H buffer).
// ---------------------------------------------------------------------------
#define BKK 64
#define STAGES 3
#define LDT 72
#define HST 131   // fp32 staging stride: 131 % 32 = 3 (coprime) -> clean LDS

template <int MI, int NI, int OCC, bool KAN>
__global__ void __launch_bounds__(128, OCC)
gemm_mma(const __nv_bfloat16* __restrict__ A, const __nv_bfloat16* __restrict__ B,
         float* __restrict__ C, __nv_bfloat16* __restrict__ A2,
         const float* __restrict__ gridk, int Nout, int K) {
    constexpr int BM_ = 2 * MI * 16;
    constexpr int BN_ = 2 * NI * 8;
    constexpr int TILE_A = BM_ * LDT;
    constexpr int TILE_B = BN_ * LDT;
    extern __shared__ __nv_bfloat16 sm[];
    const uint32_t sm_base = cvta_smem(sm);

    const int tid = threadIdx.x;
    const int lane = tid & 31;
    const int wid = tid >> 5;
    const int wm = wid >> 1;
    const int wn = wid & 1;
    const int m0 = blockIdx.y * BM_;
    const int n0 = blockIdx.x * BN_;

    const __nv_bfloat16* Ag = A + (size_t)m0 * K;
    const __nv_bfloat16* Bg = B + (size_t)n0 * K;

    const int lrow = tid >> 3;
    const int lcol = (tid & 7) * 8;

    const int nk = K / BKK;

    auto stage_load = [&](int ks) {
        const int buf = ks % STAGES;
        const size_t koff = (size_t)ks * BKK + lcol;
        const uint32_t abase = sm_base + (uint32_t)(buf * (TILE_A + TILE_B)) * 2;
        const uint32_t bbase = abase + (uint32_t)TILE_A * 2;
#pragma unroll
        for (int r = 0; r < BM_; r += 16)
            cp16(abase + (uint32_t)((lrow + r) * LDT + lcol) * 2,
                 Ag + (size_t)(lrow + r) * K + koff);
#pragma unroll
        for (int r = 0; r < BN_; r += 16)
            cp16(bbase + (uint32_t)((lrow + r) * LDT + lcol) * 2,
                 Bg + (size_t)(lrow + r) * K + koff);
        cp_commit();
    };

    float acc[MI][NI][4];
#pragma unroll
    for (int i = 0; i < MI; i++)
#pragma unroll
        for (int j = 0; j < NI; j++)
#pragma unroll
            for (int e = 0; e < 4; e++) acc[i][j][e] = 0.0f;

    const int lm_row = lane & 15;
    const int lm_koff = (lane >> 4) * 8;

    uint32_t afr[2][MI][4];
    uint32_t bfr[2][NI / 2][4];

    stage_load(0);
    stage_load(1);

    for (int ks = 0; ks < nk; ks++) {
        if (ks + 1 < nk) cp_wait<1>(); else cp_wait<0>();
        __syncthreads();
        if (ks + 2 < nk) stage_load(ks + 2);

        const int buf = ks % STAGES;
        const uint32_t abase = sm_base + (uint32_t)(buf * (TILE_A + TILE_B)) * 2 +
                               (uint32_t)((wm * MI * 16 + lm_row) * LDT + lm_koff) * 2;
        const uint32_t bbase = sm_base + (uint32_t)(buf * (TILE_A + TILE_B) + TILE_A) * 2 +
                               (uint32_t)((wn * NI * 8 + lm_row) * LDT + lm_koff) * 2;

#pragma unroll
        for (int mi = 0; mi < MI; mi++)
            ldmx4(afr[0][mi], abase + (uint32_t)(mi * 16 * LDT) * 2);
#pragma unroll
        for (int g = 0; g < NI / 2; g++)
            ldmx4(bfr[0][g], bbase + (uint32_t)(g * 16 * LDT) * 2);

#pragma unroll
        for (int kf = 0; kf < 4; kf++) {
            const int cur = kf & 1, nxt = cur ^ 1;
            if (kf < 3) {
                const uint32_t ka = abase + (uint32_t)((kf + 1) * 16) * 2;
                const uint32_t kb = bbase + (uint32_t)((kf + 1) * 16) * 2;
#pragma unroll
                for (int mi = 0; mi < MI; mi++)
                    ldmx4(afr[nxt][mi], ka + (uint32_t)(mi * 16 * LDT) * 2);
#pragma unroll
                for (int g = 0; g < NI / 2; g++)
                    ldmx4(bfr[nxt][g], kb + (uint32_t)(g * 16 * LDT) * 2);
            }
#pragma unroll
            for (int mi = 0; mi < MI; mi++)
#pragma unroll
                for (int ni = 0; ni < NI; ni++) {
                    const int g = ni >> 1, o = ni & 1;
                    mma16816(acc[mi][ni], afr[cur][mi], bfr[cur][g][o], bfr[cur][g][o + 2]);
                }
        }
    }

    const int erow = lane >> 2;
    const int ecol = (lane & 3) * 2;

    if (KAN) {
        // --- fused layer-2 expansion via SMEM staging ---
        __syncthreads();                         // all ldmx4 done; reuse smem
        float* hs = reinterpret_cast<float*>(sm);
#pragma unroll
        for (int mi = 0; mi < MI; mi++)
#pragma unroll
            for (int ni = 0; ni < NI; ni++) {
                const int r = wm * MI * 16 + mi * 16 + erow;
                const int c = wn * NI * 8 + ni * 8 + ecol;
                hs[r * HST + c]           = acc[mi][ni][0];
                hs[r * HST + c + 1]       = acc[mi][ni][1];
                hs[(r + 8) * HST + c]     = acc[mi][ni][2];
                hs[(r + 8) * HST + c + 1] = acc[mi][ni][3];
            }
        __syncthreads();

        const float t0 = __ldg(gridk);
        const float ih = __fdividef(1.0f, __ldg(gridk + 1) - t0);
        __nv_bfloat16* rowp = A2 + (size_t)(m0 + tid) * K2P;
        const int off = D_FF * 8;
#pragma unroll 4
        for (int c = 0; c < BN_; c++) {
            float v = hs[tid * HST + c];
            __nv_bfloat16 sh, sl;
            uint4 pk;
            expand_one(v, t0, ih, sh, sl, pk);
            const int gc = n0 + c;
            *(uint4*)(rowp + gc * 8) = pk;
            rowp[off + gc]             = sh;
            rowp[off + D_FF + gc]      = sh;
            rowp[off + 2 * D_FF + gc]  = sl;
        }
    } else {
#pragma unroll
        for (int mi = 0; mi < MI; mi++) {
#pragma unroll
            for (int ni = 0; ni < NI; ni++) {
                const int row = m0 + wm * MI * 16 + mi * 16 + erow;
                const int col = n0 + wn * NI * 8 + ni * 8 + ecol;
                float* p0 = C + (size_t)row * Nout + col;
                float* p1 = C + (size_t)(row + 8) * Nout + col;
                *(float2*)p0 = make_float2(acc[mi][ni][0], acc[mi][ni][1]);
                *(float2*)p1 = make_float2(acc[mi][ni][2], acc[mi][ni][3]);
            }
        }
    }
}

// ---------------------------------------------------------------------------
// Launch
// ---------------------------------------------------------------------------
extern "C" void kernel_launch(void* const* d_in, const int* in_sizes, int n_in,
                              void* d_out, int out_size) {
    const float* x    = (const float*)d_in[0];
    const float* grid = (const float*)d_in[1];
    const float* w1b  = (const float*)d_in[2];
    const float* w1s  = (const float*)d_in[3];
    const float* w2b  = (const float*)d_in[4];
    const float* w2s  = (const float*)d_in[5];
    float* out = (float*)d_out;

    const int ntok = in_sizes[0] / D_MODEL;  // 4096

    __nv_bfloat16 *A1, *A2, *W1, *W2;
    cudaGetSymbolAddress((void**)&A1, g_A1);
    cudaGetSymbolAddress((void**)&A2, g_A2);
    cudaGetSymbolAddress((void**)&W1, g_W1);
    cudaGetSymbolAddress((void**)&W2, g_W2);

    // gemm1 smem: max(pipeline 110592, staging 128*131*4 = 67072) = 110592
    const int smem1 = STAGES * (128 + 128) * LDT * 2;  // 110592
    const int smem2 = STAGES * (64 + 64) * LDT * 2;    //  55296
    cudaFuncSetAttribute((const void*)gemm_mma<4, 8, 2, true>,
                         cudaFuncAttributeMaxDynamicSharedMemorySize, smem1);
    cudaFuncSetAttribute((const void*)gemm_mma<2, 4, 4, false>,
                         cudaFuncAttributeMaxDynamicSharedMemorySize, smem2);

    // ---- fused preprocessing ----
    prep_kernel<<<NB1 + NB2 + NB3, 256>>>(x, grid, w1b, w1s, w2b, w2s, W1, W2, A1);

    // ---- layer 1 GEMM + fused layer-2 expansion epilogue ----
    dim3 grid1(D_FF / 128, ntok / 128);
    gemm_mma<4, 8, 2, true><<<grid1, 128, smem1>>>(A1, W1, nullptr, A2, grid, D_FF, K1P);

    // ---- layer 2 GEMM ----
    dim3 grid2(D_MODEL / 64, ntok / 64);
    gemm_mma<2, 4, 4, false><<<grid2, 128, smem2>>>(A2, W2, out, nullptr, nullptr, D_MODEL, K2P);
}

// round 13
// speedup vs baseline: 1.3971x; 1.3971x over previous
#include <cuda_runtime.h>
#include <cuda_bf16.h>
#include <math.h>
#include <stdint.h>

#define D_MODEL 512
#define D_FF    2048
#define GKN     8
#define NTOK    4096

#define K1P (D_MODEL * GKN + 3 * D_MODEL)   // 5632
#define K2P (D_FF * GKN + 3 * D_FF)         // 22528

__device__ __nv_bfloat16 g_A1[(size_t)NTOK * K1P];
__device__ __nv_bfloat16 g_A2[(size_t)NTOK * K2P];
__device__ __nv_bfloat16 g_W1[(size_t)D_FF * K1P];
__device__ __nv_bfloat16 g_W2[(size_t)D_MODEL * K2P];
__device__ float         g_H [(size_t)NTOK * D_FF];

// ---------------------------------------------------------------------------
// PTX helpers (arch-agnostic on .target sm_103)
// ---------------------------------------------------------------------------
__device__ __forceinline__ uint32_t cvta_smem(const void* p) {
    uint32_t a;
    asm("{ .reg .u64 t; cvta.to.shared.u64 t, %1; cvt.u32.u64 %0, t; }" : "=r"(a) : "l"(p));
    return a;
}
__device__ __forceinline__ void cp16(uint32_t s, const void* g) {
    asm volatile("cp.async.cg.shared.global [%0], [%1], 16;" :: "r"(s), "l"(g));
}
__device__ __forceinline__ void cp_commit() {
    asm volatile("cp.async.commit_group;" ::: "memory");
}
template <int N>
__device__ __forceinline__ void cp_wait() {
    asm volatile("cp.async.wait_group %0;" :: "n"(N) : "memory");
}
__device__ __forceinline__ void ldmx4(uint32_t* r, uint32_t a) {
    asm volatile("ldmatrix.sync.aligned.m8n8.x4.shared.b16 {%0,%1,%2,%3}, [%4];"
                 : "=r"(r[0]), "=r"(r[1]), "=r"(r[2]), "=r"(r[3]) : "r"(a));
}
__device__ __forceinline__ void mma16816(float* d, const uint32_t* a, uint32_t b0, uint32_t b1) {
    asm volatile(
        "mma.sync.aligned.m16n8k16.row.col.f32.bf16.bf16.f32 "
        "{%0,%1,%2,%3}, {%4,%5,%6,%7}, {%8,%9}, {%0,%1,%2,%3};"
        : "+f"(d[0]), "+f"(d[1]), "+f"(d[2]), "+f"(d[3])
        : "r"(a[0]), "r"(a[1]), "r"(a[2]), "r"(a[3]), "r"(b0), "r"(b1));
}

// ---------------------------------------------------------------------------
// Closed-form uniform cubic B-spline expansion (cardinal N3 translates).
// ---------------------------------------------------------------------------
__device__ __forceinline__ void expand_one(float v, float t0, float ih,
                                           __nv_bfloat16& sh, __nv_bfloat16& sl,
                                           uint4& pk) {
    float s = v * __fdividef(1.0f, 1.0f + __expf(-v));
    sh = __float2bfloat16(s);
    sl = __float2bfloat16(s - __bfloat162float(sh));

    float u = (v - t0) * ih;
    float jf = floorf(u);
    int j0 = (int)jf;
    float w = u - jf;
    float w2 = w * w, w3 = w2 * w;
    const float k6 = 1.0f / 6.0f;
    float c3 = w3 * k6;
    float c2 = k6 * (1.0f + 3.0f * w + 3.0f * w2 - 3.0f * w3);
    float c1 = k6 * (4.0f - 6.0f * w2 + 3.0f * w3);
    float c0 = k6 * (1.0f - 3.0f * w + 3.0f * w2 - w3);

    float bq[8];
#pragma unroll
    for (int q = 0; q < 8; q++) {
        int d = j0 - q;
        float val = 0.0f;
        val = (d == 0) ? c3 : val;
        val = (d == 1) ? c2 : val;
        val = (d == 2) ? c1 : val;
        val = (d == 3) ? c0 : val;
        bq[q] = val;
    }

    __nv_bfloat162 p0 = __floats2bfloat162_rn(bq[0], bq[1]);
    __nv_bfloat162 p1 = __floats2bfloat162_rn(bq[2], bq[3]);
    __nv_bfloat162 p2 = __floats2bfloat162_rn(bq[4], bq[5]);
    __nv_bfloat162 p3 = __floats2bfloat162_rn(bq[6], bq[7]);
    pk.x = *(uint32_t*)&p0; pk.y = *(uint32_t*)&p1;
    pk.z = *(uint32_t*)&p2; pk.w = *(uint32_t*)&p3;
}

// ---------------------------------------------------------------------------
// Per-element job bodies (prep)
// ---------------------------------------------------------------------------
__device__ __forceinline__ void do_expand(const float* __restrict__ x,
                                          float t0, float ih,
                                          __nv_bfloat16* __restrict__ pA,
                                          int idx, int in_log2, int strideK) {
    const int IN = 1 << in_log2;
    const int row = idx >> in_log2;
    const int i = idx & (IN - 1);

    __nv_bfloat16 sh, sl;
    uint4 pk;
    expand_one(x[idx], t0, ih, sh, sl, pk);

    __nv_bfloat16* rowp = pA + (size_t)row * strideK;
    *(uint4*)(rowp + i * 8) = pk;
    const int off = IN * 8;
    rowp[off + i]          = sh;
    rowp[off + IN + i]     = sh;
    rowp[off + 2 * IN + i] = sl;
}

__device__ __forceinline__ void do_pack_w(const float* __restrict__ wb,
                                          const float* __restrict__ ws,
                                          __nv_bfloat16* __restrict__ pW,
                                          int idx, int in_log2, int strideK) {
    const int IN = 1 << in_log2;
    const int o = idx >> in_log2;
    const int i = idx & (IN - 1);

    float base = wb[idx];
    __nv_bfloat16 hi = __float2bfloat16(base);
    __nv_bfloat16 lo = __float2bfloat16(base - __bfloat162float(hi));

    float4 s0 = ((const float4*)ws)[idx * 2];
    float4 s1 = ((const float4*)ws)[idx * 2 + 1];
    __nv_bfloat162 p0 = __floats2bfloat162_rn(s0.x, s0.y);
    __nv_bfloat162 p1 = __floats2bfloat162_rn(s0.z, s0.w);
    __nv_bfloat162 p2 = __floats2bfloat162_rn(s1.x, s1.y);
    __nv_bfloat162 p3 = __floats2bfloat162_rn(s1.z, s1.w);
    uint4 pk;
    pk.x = *(uint32_t*)&p0; pk.y = *(uint32_t*)&p1;
    pk.z = *(uint32_t*)&p2; pk.w = *(uint32_t*)&p3;

    __nv_bfloat16* rowp = pW + (size_t)o * strideK;
    *(uint4*)(rowp + i * 8) = pk;
    const int off = IN * 8;
    rowp[off + i]          = hi;
    rowp[off + IN + i]     = lo;
    rowp[off + 2 * IN + i] = hi;
}

// ---------------------------------------------------------------------------
// Fused preprocessing: pack W1, pack W2, expand layer-1 input, zero out.
// ---------------------------------------------------------------------------
#define NB1 (D_FF * D_MODEL / 256)           // 4096
#define NB2 (D_MODEL * D_FF / 256)           // 4096
#define NB3 (NTOK * D_MODEL / 256)           // 8192
#define NB4 (NTOK * D_MODEL / 256)           // 8192 (zero out: 4096*512 floats)

__global__ void __launch_bounds__(256)
prep_kernel(const float* __restrict__ x, const float* __restrict__ grid,
            const float* __restrict__ w1b, const float* __restrict__ w1s,
            const float* __restrict__ w2b, const float* __restrict__ w2s,
            __nv_bfloat16* __restrict__ W1, __nv_bfloat16* __restrict__ W2,
            __nv_bfloat16* __restrict__ A1, float* __restrict__ outz) {
    const int b = blockIdx.x;
    if (b < NB1) {
        int idx = b * 256 + threadIdx.x;
        do_pack_w(w1b, w1s, W1, idx, 9, K1P);
    } else if (b < NB1 + NB2) {
        int idx = (b - NB1) * 256 + threadIdx.x;
        do_pack_w(w2b, w2s, W2, idx, 11, K2P);
    } else if (b < NB1 + NB2 + NB3) {
        int idx = (b - NB1 - NB2) * 256 + threadIdx.x;
        const float t0 = __ldg(grid);
        const float ih = __fdividef(1.0f, __ldg(grid + 1) - t0);
        do_expand(x, t0, ih, A1, idx, 9, K1P);
    } else {
        int idx = (b - NB1 - NB2 - NB3) * 256 + threadIdx.x;
        outz[idx] = 0.0f;
    }
}

// ---------------------------------------------------------------------------
// Layer-2 expansion (standalone, coalesced writes).
// ---------------------------------------------------------------------------
__global__ void __launch_bounds__(256)
expand2_kernel(const float* __restrict__ h, const float* __restrict__ grid,
               __nv_bfloat16* __restrict__ A2, int total) {
    int idx = blockIdx.x * blockDim.x + threadIdx.x;
    if (idx >= total) return;
    const float t0 = __ldg(grid);
    const float ih = __fdividef(1.0f, __ldg(grid + 1) - t0);
    do_expand(h, t0, ih, A2, idx, 11, K2P);
}

// ---------------------------------------------------------------------------
// bf16 mma.sync GEMM: C(M,Nout) (+)= A(M,K) * B(Nout,K)^T, fp32 accumulate.
// Warp grid WR x WC (WR*WC warps), warp tile (MI*16) x (NI*8).
// BK=64, 3-stage cp.async, one __syncthreads per K-iter, frag double-buffer.
// SPLITK: blockIdx.z selects K-half; epilogue uses atomicAdd (C pre-zeroed).
// ---------------------------------------------------------------------------
#define BKK 64
#define STAGES 3
#define LDT 72

template <int WR, int WC, int MI, int NI, int OCC, bool SPLITK>
__global__ void __launch_bounds__(WR * WC * 32, OCC)
gemm_mma(const __nv_bfloat16* __restrict__ A, const __nv_bfloat16* __restrict__ B,
         float* __restrict__ C, int Nout, int K) {
    constexpr int THREADS = WR * WC * 32;
    constexpr int BM_ = WR * MI * 16;
    constexpr int BN_ = WC * NI * 8;
    constexpr int TILE_A = BM_ * LDT;
    constexpr int TILE_B = BN_ * LDT;
    constexpr int RP = THREADS / 8;   // rows loaded per pass
    extern __shared__ __nv_bfloat16 sm[];
    const uint32_t sm_base = cvta_smem(sm);

    const int tid = threadIdx.x;
    const int lane = tid & 31;
    const int wid = tid >> 5;
    const int wm = wid / WC;
    const int wn = wid % WC;
    const int m0 = blockIdx.y * BM_;
    const int n0 = blockIdx.x * BN_;

    const int kseg = SPLITK ? (K >> 1) : K;
    const size_t koff0 = SPLITK ? (size_t)blockIdx.z * kseg : 0;

    const __nv_bfloat16* Ag = A + (size_t)m0 * K + koff0;
    const __nv_bfloat16* Bg = B + (size_t)n0 * K + koff0;

    const int lrow = tid >> 3;
    const int lcol = (tid & 7) * 8;

    const int nk = kseg / BKK;

    auto stage_load = [&](int ks) {
        const int buf = ks % STAGES;
        const size_t koff = (size_t)ks * BKK + lcol;
        const uint32_t abase = sm_base + (uint32_t)(buf * (TILE_A + TILE_B)) * 2;
        const uint32_t bbase = abase + (uint32_t)TILE_A * 2;
#pragma unroll
        for (int r = 0; r < BM_; r += RP)
            cp16(abase + (uint32_t)((lrow + r) * LDT + lcol) * 2,
                 Ag + (size_t)(lrow + r) * K + koff);
#pragma unroll
        for (int r = 0; r < BN_; r += RP)
            cp16(bbase + (uint32_t)((lrow + r) * LDT + lcol) * 2,
                 Bg + (size_t)(lrow + r) * K + koff);
        cp_commit();
    };

    float acc[MI][NI][4];
#pragma unroll
    for (int i = 0; i < MI; i++)
#pragma unroll
        for (int j = 0; j < NI; j++)
#pragma unroll
            for (int e = 0; e < 4; e++) acc[i][j][e] = 0.0f;

    const int lm_row = lane & 15;
    const int lm_koff = (lane >> 4) * 8;

    uint32_t afr[2][MI][4];
    uint32_t bfr[2][NI / 2][4];

    stage_load(0);
    stage_load(1);

    for (int ks = 0; ks < nk; ks++) {
        if (ks + 1 < nk) cp_wait<1>(); else cp_wait<0>();
        __syncthreads();
        if (ks + 2 < nk) stage_load(ks + 2);

        const int buf = ks % STAGES;
        const uint32_t abase = sm_base + (uint32_t)(buf * (TILE_A + TILE_B)) * 2 +
                               (uint32_t)((wm * MI * 16 + lm_row) * LDT + lm_koff) * 2;
        const uint32_t bbase = sm_base + (uint32_t)(buf * (TILE_A + TILE_B) + TILE_A) * 2 +
                               (uint32_t)((wn * NI * 8 + lm_row) * LDT + lm_koff) * 2;

#pragma unroll
        for (int mi = 0; mi < MI; mi++)
            ldmx4(afr[0][mi], abase + (uint32_t)(mi * 16 * LDT) * 2);
#pragma unroll
        for (int g = 0; g < NI / 2; g++)
            ldmx4(bfr[0][g], bbase + (uint32_t)(g * 16 * LDT) * 2);

#pragma unroll
        for (int kf = 0; kf < 4; kf++) {
            const int cur = kf & 1, nxt = cur ^ 1;
            if (kf < 3) {
                const uint32_t ka = abase + (uint32_t)((kf + 1) * 16) * 2;
                const uint32_t kb = bbase + (uint32_t)((kf + 1) * 16) * 2;
#pragma unroll
                for (int mi = 0; mi < MI; mi++)
                    ldmx4(afr[nxt][mi], ka + (uint32_t)(mi * 16 * LDT) * 2);
#pragma unroll
                for (int g = 0; g < NI / 2; g++)
                    ldmx4(bfr[nxt][g], kb + (uint32_t)(g * 16 * LDT) * 2);
            }
#pragma unroll
            for (int mi = 0; mi < MI; mi++)
#pragma unroll
                for (int ni = 0; ni < NI; ni++) {
                    const int g = ni >> 1, o = ni & 1;
                    mma16816(acc[mi][ni], afr[cur][mi], bfr[cur][g][o], bfr[cur][g][o + 2]);
                }
        }
    }

    // epilogue
    const int erow = lane >> 2;
    const int ecol = (lane & 3) * 2;
#pragma unroll
    for (int mi = 0; mi < MI; mi++) {
#pragma unroll
        for (int ni = 0; ni < NI; ni++) {
            const int row = m0 + wm * MI * 16 + mi * 16 + erow;
            const int col = n0 + wn * NI * 8 + ni * 8 + ecol;
            float* p0 = C + (size_t)row * Nout + col;
            float* p1 = C + (size_t)(row + 8) * Nout + col;
            if (SPLITK) {
                atomicAdd(p0,     acc[mi][ni][0]);
                atomicAdd(p0 + 1, acc[mi][ni][1]);
                atomicAdd(p1,     acc[mi][ni][2]);
                atomicAdd(p1 + 1, acc[mi][ni][3]);
            } else {
                *(float2*)p0 = make_float2(acc[mi][ni][0], acc[mi][ni][1]);
                *(float2*)p1 = make_float2(acc[mi][ni][2], acc[mi][ni][3]);
            }
        }
    }
}

// ---------------------------------------------------------------------------
// Launch
// ---------------------------------------------------------------------------
extern "C" void kernel_launch(void* const* d_in, const int* in_sizes, int n_in,
                              void* d_out, int out_size) {
    const float* x    = (const float*)d_in[0];
    const float* grid = (const float*)d_in[1];
    const float* w1b  = (const float*)d_in[2];
    const float* w1s  = (const float*)d_in[3];
    const float* w2b  = (const float*)d_in[4];
    const float* w2s  = (const float*)d_in[5];
    float* out = (float*)d_out;

    const int ntok = in_sizes[0] / D_MODEL;  // 4096

    __nv_bfloat16 *A1, *A2, *W1, *W2;
    float* H;
    cudaGetSymbolAddress((void**)&A1, g_A1);
    cudaGetSymbolAddress((void**)&A2, g_A2);
    cudaGetSymbolAddress((void**)&W1, g_W1);
    cudaGetSymbolAddress((void**)&W2, g_W2);
    cudaGetSymbolAddress((void**)&H,  g_H);

    // gemm1: 8 warps (2x4), warp 64x64 -> CTA 128x256, OCC=1
    // gemm2: 4 warps (2x2), warp 64x64 -> CTA 128x128, OCC=2, split-K=2
    const int smem1 = STAGES * (128 + 256) * LDT * 2;  // 165888
    const int smem2 = STAGES * (128 + 128) * LDT * 2;  // 110592
    cudaFuncSetAttribute((const void*)gemm_mma<2, 4, 4, 8, 1, false>,
                         cudaFuncAttributeMaxDynamicSharedMemorySize, smem1);
    cudaFuncSetAttribute((const void*)gemm_mma<2, 2, 4, 8, 2, true>,
                         cudaFuncAttributeMaxDynamicSharedMemorySize, smem2);

    // ---- fused preprocessing (incl. zeroing out for split-K atomics) ----
    prep_kernel<<<NB1 + NB2 + NB3 + NB4, 256>>>(x, grid, w1b, w1s, w2b, w2s,
                                                W1, W2, A1, out);

    // ---- layer 1 GEMM: 128x256 tiles ----
    dim3 grid1(D_FF / 256, ntok / 128);
    gemm_mma<2, 4, 4, 8, 1, false><<<grid1, 256, smem1>>>(A1, W1, H, D_FF, K1P);

    // ---- layer 2 expansion ----
    const int tot2 = ntok * D_FF;
    expand2_kernel<<<(tot2 + 255) / 256, 256>>>(H, grid, A2, tot2);

    // ---- layer 2 GEMM: 128x128 tiles, split-K=2, atomic accumulate ----
    dim3 grid2(D_MODEL / 128, ntok / 128, 2);
    gemm_mma<2, 2, 4, 8, 2, true><<<grid2, 128, smem2>>>(A2, W2, out, D_MODEL, K2P);
}

// round 14
// speedup vs baseline: 1.4365x; 1.0282x over previous
#include <cuda_runtime.h>
#include <cuda_bf16.h>
#include <math.h>
#include <stdint.h>

#define D_MODEL 512
#define D_FF    2048
#define GKN     8
#define NTOK    4096

#define K1P (D_MODEL * GKN + 3 * D_MODEL)   // 5632
#define K2P (D_FF * GKN + 3 * D_FF)         // 22528

__device__ __nv_bfloat16 g_A1[(size_t)NTOK * K1P];
__device__ __nv_bfloat16 g_A2[(size_t)NTOK * K2P];
__device__ __nv_bfloat16 g_W1[(size_t)D_FF * K1P];
__device__ __nv_bfloat16 g_W2[(size_t)D_MODEL * K2P];

// ---------------------------------------------------------------------------
// PTX helpers (arch-agnostic on .target sm_103)
// ---------------------------------------------------------------------------
__device__ __forceinline__ uint32_t cvta_smem(const void* p) {
    uint32_t a;
    asm("{ .reg .u64 t; cvta.to.shared.u64 t, %1; cvt.u32.u64 %0, t; }" : "=r"(a) : "l"(p));
    return a;
}
__device__ __forceinline__ void cp16(uint32_t s, const void* g) {
    asm volatile("cp.async.cg.shared.global [%0], [%1], 16;" :: "r"(s), "l"(g));
}
__device__ __forceinline__ void cp_commit() {
    asm volatile("cp.async.commit_group;" ::: "memory");
}
template <int N>
__device__ __forceinline__ void cp_wait() {
    asm volatile("cp.async.wait_group %0;" :: "n"(N) : "memory");
}
__device__ __forceinline__ void ldmx4(uint32_t* r, uint32_t a) {
    asm volatile("ldmatrix.sync.aligned.m8n8.x4.shared.b16 {%0,%1,%2,%3}, [%4];"
                 : "=r"(r[0]), "=r"(r[1]), "=r"(r[2]), "=r"(r[3]) : "r"(a));
}
__device__ __forceinline__ void mma16816(float* d, const uint32_t* a, uint32_t b0, uint32_t b1) {
    asm volatile(
        "mma.sync.aligned.m16n8k16.row.col.f32.bf16.bf16.f32 "
        "{%0,%1,%2,%3}, {%4,%5,%6,%7}, {%8,%9}, {%0,%1,%2,%3};"
        : "+f"(d[0]), "+f"(d[1]), "+f"(d[2]), "+f"(d[3])
        : "r"(a[0]), "r"(a[1]), "r"(a[2]), "r"(a[3]), "r"(b0), "r"(b1));
}

// ---------------------------------------------------------------------------
// Closed-form uniform cubic B-spline expansion (cardinal N3 translates).
// ---------------------------------------------------------------------------
__device__ __forceinline__ void expand_one(float v, float t0, float ih,
                                           __nv_bfloat16& sh, __nv_bfloat16& sl,
                                           uint4& pk) {
    float s = v * __fdividef(1.0f, 1.0f + __expf(-v));
    sh = __float2bfloat16(s);
    sl = __float2bfloat16(s - __bfloat162float(sh));

    float u = (v - t0) * ih;
    float jf = floorf(u);
    int j0 = (int)jf;
    float w = u - jf;
    float w2 = w * w, w3 = w2 * w;
    const float k6 = 1.0f / 6.0f;
    float c3 = w3 * k6;
    float c2 = k6 * (1.0f + 3.0f * w + 3.0f * w2 - 3.0f * w3);
    float c1 = k6 * (4.0f - 6.0f * w2 + 3.0f * w3);
    float c0 = k6 * (1.0f - 3.0f * w + 3.0f * w2 - w3);

    float bq[8];
#pragma unroll
    for (int q = 0; q < 8; q++) {
        int d = j0 - q;
        float val = 0.0f;
        val = (d == 0) ? c3 : val;
        val = (d == 1) ? c2 : val;
        val = (d == 2) ? c1 : val;
        val = (d == 3) ? c0 : val;
        bq[q] = val;
    }

    __nv_bfloat162 p0 = __floats2bfloat162_rn(bq[0], bq[1]);
    __nv_bfloat162 p1 = __floats2bfloat162_rn(bq[2], bq[3]);
    __nv_bfloat162 p2 = __floats2bfloat162_rn(bq[4], bq[5]);
    __nv_bfloat162 p3 = __floats2bfloat162_rn(bq[6], bq[7]);
    pk.x = *(uint32_t*)&p0; pk.y = *(uint32_t*)&p1;
    pk.z = *(uint32_t*)&p2; pk.w = *(uint32_t*)&p3;
}

// ---------------------------------------------------------------------------
// Per-element job bodies (prep)
// ---------------------------------------------------------------------------
__device__ __forceinline__ void do_expand(const float* __restrict__ x,
                                          float t0, float ih,
                                          __nv_bfloat16* __restrict__ pA,
                                          int idx, int in_log2, int strideK) {
    const int IN = 1 << in_log2;
    const int row = idx >> in_log2;
    const int i = idx & (IN - 1);

    __nv_bfloat16 sh, sl;
    uint4 pk;
    expand_one(x[idx], t0, ih, sh, sl, pk);

    __nv_bfloat16* rowp = pA + (size_t)row * strideK;
    *(uint4*)(rowp + i * 8) = pk;
    const int off = IN * 8;
    rowp[off + i]          = sh;
    rowp[off + IN + i]     = sh;
    rowp[off + 2 * IN + i] = sl;
}

__device__ __forceinline__ void do_pack_w(const float* __restrict__ wb,
                                          const float* __restrict__ ws,
                                          __nv_bfloat16* __restrict__ pW,
                                          int idx, int in_log2, int strideK) {
    const int IN = 1 << in_log2;
    const int o = idx >> in_log2;
    const int i = idx & (IN - 1);

    float base = wb[idx];
    __nv_bfloat16 hi = __float2bfloat16(base);
    __nv_bfloat16 lo = __float2bfloat16(base - __bfloat162float(hi));

    float4 s0 = ((const float4*)ws)[idx * 2];
    float4 s1 = ((const float4*)ws)[idx * 2 + 1];
    __nv_bfloat162 p0 = __floats2bfloat162_rn(s0.x, s0.y);
    __nv_bfloat162 p1 = __floats2bfloat162_rn(s0.z, s0.w);
    __nv_bfloat162 p2 = __floats2bfloat162_rn(s1.x, s1.y);
    __nv_bfloat162 p3 = __floats2bfloat162_rn(s1.z, s1.w);
    uint4 pk;
    pk.x = *(uint32_t*)&p0; pk.y = *(uint32_t*)&p1;
    pk.z = *(uint32_t*)&p2; pk.w = *(uint32_t*)&p3;

    __nv_bfloat16* rowp = pW + (size_t)o * strideK;
    *(uint4*)(rowp + i * 8) = pk;
    const int off = IN * 8;
    rowp[off + i]          = hi;
    rowp[off + IN + i]     = lo;
    rowp[off + 2 * IN + i] = hi;
}

// ---------------------------------------------------------------------------
// Fused preprocessing: pack W1, pack W2, expand layer-1 input, zero out.
// ---------------------------------------------------------------------------
#define NB1 (D_FF * D_MODEL / 256)           // 4096
#define NB2 (D_MODEL * D_FF / 256)           // 4096
#define NB3 (NTOK * D_MODEL / 256)           // 8192
#define NB4 (NTOK * D_MODEL / 256)           // 8192 (zero out)

__global__ void __launch_bounds__(256)
prep_kernel(const float* __restrict__ x, const float* __restrict__ grid,
            const float* __restrict__ w1b, const float* __restrict__ w1s,
            const float* __restrict__ w2b, const float* __restrict__ w2s,
            __nv_bfloat16* __restrict__ W1, __nv_bfloat16* __restrict__ W2,
            __nv_bfloat16* __restrict__ A1, float* __restrict__ outz) {
    const int b = blockIdx.x;
    if (b < NB1) {
        int idx = b * 256 + threadIdx.x;
        do_pack_w(w1b, w1s, W1, idx, 9, K1P);
    } else if (b < NB1 + NB2) {
        int idx = (b - NB1) * 256 + threadIdx.x;
        do_pack_w(w2b, w2s, W2, idx, 11, K2P);
    } else if (b < NB1 + NB2 + NB3) {
        int idx = (b - NB1 - NB2) * 256 + threadIdx.x;
        const float t0 = __ldg(grid);
        const float ih = __fdividef(1.0f, __ldg(grid + 1) - t0);
        do_expand(x, t0, ih, A1, idx, 9, K1P);
    } else {
        int idx = (b - NB1 - NB2 - NB3) * 256 + threadIdx.x;
        outz[idx] = 0.0f;
    }
}

// ---------------------------------------------------------------------------
// bf16 mma.sync GEMM: C(M,Nout) (+)= A(M,K) * B(Nout,K)^T, fp32 accumulate.
// Warp grid WR x WC, warp tile (MI*16) x (NI*8). BK=64, 3-stage cp.async,
// one __syncthreads per K-iter, fragment double-buffering.
// SPLITK: blockIdx.z selects K-half; atomicAdd epilogue (C pre-zeroed).
// KAN: fused layer-2 expansion epilogue — stage acc (=h) in SMEM, then one
//      WARP PER ROW / lanes across columns -> fully coalesced A2 stores.
// ---------------------------------------------------------------------------
#define BKK 64
#define STAGES 3
#define LDT 72
#define HS 260    // fp32 staging stride (260 % 32 = 4)

template <int WR, int WC, int MI, int NI, int OCC, bool SPLITK, bool KAN>
__global__ void __launch_bounds__(WR * WC * 32, OCC)
gemm_mma(const __nv_bfloat16* __restrict__ A, const __nv_bfloat16* __restrict__ B,
         float* __restrict__ C, __nv_bfloat16* __restrict__ A2,
         const float* __restrict__ gridk, int Nout, int K) {
    constexpr int THREADS = WR * WC * 32;
    constexpr int NWARP = WR * WC;
    constexpr int BM_ = WR * MI * 16;
    constexpr int BN_ = WC * NI * 8;
    constexpr int TILE_A = BM_ * LDT;
    constexpr int TILE_B = BN_ * LDT;
    constexpr int RP = THREADS / 8;
    extern __shared__ __nv_bfloat16 sm[];
    const uint32_t sm_base = cvta_smem(sm);

    const int tid = threadIdx.x;
    const int lane = tid & 31;
    const int wid = tid >> 5;
    const int wm = wid / WC;
    const int wn = wid % WC;
    const int m0 = blockIdx.y * BM_;
    const int n0 = blockIdx.x * BN_;

    const int kseg = SPLITK ? (K >> 1) : K;
    const size_t koff0 = SPLITK ? (size_t)blockIdx.z * kseg : 0;

    const __nv_bfloat16* Ag = A + (size_t)m0 * K + koff0;
    const __nv_bfloat16* Bg = B + (size_t)n0 * K + koff0;

    const int lrow = tid >> 3;
    const int lcol = (tid & 7) * 8;

    const int nk = kseg / BKK;

    auto stage_load = [&](int ks) {
        const int buf = ks % STAGES;
        const size_t koff = (size_t)ks * BKK + lcol;
        const uint32_t abase = sm_base + (uint32_t)(buf * (TILE_A + TILE_B)) * 2;
        const uint32_t bbase = abase + (uint32_t)TILE_A * 2;
#pragma unroll
        for (int r = 0; r < BM_; r += RP)
            cp16(abase + (uint32_t)((lrow + r) * LDT + lcol) * 2,
                 Ag + (size_t)(lrow + r) * K + koff);
#pragma unroll
        for (int r = 0; r < BN_; r += RP)
            cp16(bbase + (uint32_t)((lrow + r) * LDT + lcol) * 2,
                 Bg + (size_t)(lrow + r) * K + koff);
        cp_commit();
    };

    float acc[MI][NI][4];
#pragma unroll
    for (int i = 0; i < MI; i++)
#pragma unroll
        for (int j = 0; j < NI; j++)
#pragma unroll
            for (int e = 0; e < 4; e++) acc[i][j][e] = 0.0f;

    const int lm_row = lane & 15;
    const int lm_koff = (lane >> 4) * 8;

    uint32_t afr[2][MI][4];
    uint32_t bfr[2][NI / 2][4];

    stage_load(0);
    stage_load(1);

    for (int ks = 0; ks < nk; ks++) {
        if (ks + 1 < nk) cp_wait<1>(); else cp_wait<0>();
        __syncthreads();
        if (ks + 2 < nk) stage_load(ks + 2);

        const int buf = ks % STAGES;
        const uint32_t abase = sm_base + (uint32_t)(buf * (TILE_A + TILE_B)) * 2 +
                               (uint32_t)((wm * MI * 16 + lm_row) * LDT + lm_koff) * 2;
        const uint32_t bbase = sm_base + (uint32_t)(buf * (TILE_A + TILE_B) + TILE_A) * 2 +
                               (uint32_t)((wn * NI * 8 + lm_row) * LDT + lm_koff) * 2;

#pragma unroll
        for (int mi = 0; mi < MI; mi++)
            ldmx4(afr[0][mi], abase + (uint32_t)(mi * 16 * LDT) * 2);
#pragma unroll
        for (int g = 0; g < NI / 2; g++)
            ldmx4(bfr[0][g], bbase + (uint32_t)(g * 16 * LDT) * 2);

#pragma unroll
        for (int kf = 0; kf < 4; kf++) {
            const int cur = kf & 1, nxt = cur ^ 1;
            if (kf < 3) {
                const uint32_t ka = abase + (uint32_t)((kf + 1) * 16) * 2;
                const uint32_t kb = bbase + (uint32_t)((kf + 1) * 16) * 2;
#pragma unroll
                for (int mi = 0; mi < MI; mi++)
                    ldmx4(afr[nxt][mi], ka + (uint32_t)(mi * 16 * LDT) * 2);
#pragma unroll
                for (int g = 0; g < NI / 2; g++)
                    ldmx4(bfr[nxt][g], kb + (uint32_t)(g * 16 * LDT) * 2);
            }
#pragma unroll
            for (int mi = 0; mi < MI; mi++)
#pragma unroll
                for (int ni = 0; ni < NI; ni++) {
                    const int g = ni >> 1, o = ni & 1;
                    mma16816(acc[mi][ni], afr[cur][mi], bfr[cur][g][o], bfr[cur][g][o + 2]);
                }
        }
    }

    const int erow = lane >> 2;
    const int ecol = (lane & 3) * 2;

    if (KAN) {
        // --- stage acc (=h) to SMEM, then coalesced fused expansion ---
        __syncthreads();
        float* hs = reinterpret_cast<float*>(sm);
#pragma unroll
        for (int mi = 0; mi < MI; mi++)
#pragma unroll
            for (int ni = 0; ni < NI; ni++) {
                const int r = wm * MI * 16 + mi * 16 + erow;
                const int c = wn * NI * 8 + ni * 8 + ecol;
                hs[r * HS + c]           = acc[mi][ni][0];
                hs[r * HS + c + 1]       = acc[mi][ni][1];
                hs[(r + 8) * HS + c]     = acc[mi][ni][2];
                hs[(r + 8) * HS + c + 1] = acc[mi][ni][3];
            }
        __syncthreads();

        const float t0 = __ldg(gridk);
        const float ih = __fdividef(1.0f, __ldg(gridk + 1) - t0);
        const int off = D_FF * 8;
        for (int r = wid; r < BM_; r += NWARP) {
            __nv_bfloat16* rowp = A2 + (size_t)(m0 + r) * K2P;
#pragma unroll
            for (int c0 = 0; c0 < BN_; c0 += 32) {
                float v = hs[r * HS + c0 + lane];
                __nv_bfloat16 sh, sl;
                uint4 pk;
                expand_one(v, t0, ih, sh, sl, pk);
                const int gc = n0 + c0 + lane;
                *(uint4*)(rowp + gc * 8) = pk;    // lanes -> consecutive 16B
                rowp[off + gc]            = sh;
                rowp[off + D_FF + gc]     = sh;
                rowp[off + 2 * D_FF + gc] = sl;
            }
        }
    } else {
#pragma unroll
        for (int mi = 0; mi < MI; mi++) {
#pragma unroll
            for (int ni = 0; ni < NI; ni++) {
                const int row = m0 + wm * MI * 16 + mi * 16 + erow;
                const int col = n0 + wn * NI * 8 + ni * 8 + ecol;
                float* p0 = C + (size_t)row * Nout + col;
                float* p1 = C + (size_t)(row + 8) * Nout + col;
                if (SPLITK) {
                    atomicAdd(p0,     acc[mi][ni][0]);
                    atomicAdd(p0 + 1, acc[mi][ni][1]);
                    atomicAdd(p1,     acc[mi][ni][2]);
                    atomicAdd(p1 + 1, acc[mi][ni][3]);
                } else {
                    *(float2*)p0 = make_float2(acc[mi][ni][0], acc[mi][ni][1]);
                    *(float2*)p1 = make_float2(acc[mi][ni][2], acc[mi][ni][3]);
                }
            }
        }
    }
}

// ---------------------------------------------------------------------------
// Launch
// ---------------------------------------------------------------------------
extern "C" void kernel_launch(void* const* d_in, const int* in_sizes, int n_in,
                              void* d_out, int out_size) {
    const float* x    = (const float*)d_in[0];
    const float* grid = (const float*)d_in[1];
    const float* w1b  = (const float*)d_in[2];
    const float* w1s  = (const float*)d_in[3];
    const float* w2b  = (const float*)d_in[4];
    const float* w2s  = (const float*)d_in[5];
    float* out = (float*)d_out;

    const int ntok = in_sizes[0] / D_MODEL;  // 4096

    __nv_bfloat16 *A1, *A2, *W1, *W2;
    cudaGetSymbolAddress((void**)&A1, g_A1);
    cudaGetSymbolAddress((void**)&A2, g_A2);
    cudaGetSymbolAddress((void**)&W1, g_W1);
    cudaGetSymbolAddress((void**)&W2, g_W2);

    // gemm1: 8 warps (2x4), CTA 128x256, OCC=1, fused KAN epilogue.
    //        smem: max(pipeline 165888, staging 128*260*4 = 133120) = 165888
    // gemm2: 4 warps (2x2), CTA 128x128, OCC=2, split-K=2, atomics.
    const int smem1 = STAGES * (128 + 256) * LDT * 2;  // 165888
    const int smem2 = STAGES * (128 + 128) * LDT * 2;  // 110592
    cudaFuncSetAttribute((const void*)gemm_mma<2, 4, 4, 8, 1, false, true>,
                         cudaFuncAttributeMaxDynamicSharedMemorySize, smem1);
    cudaFuncSetAttribute((const void*)gemm_mma<2, 2, 4, 8, 2, true, false>,
                         cudaFuncAttributeMaxDynamicSharedMemorySize, smem2);

    // ---- fused preprocessing (incl. zeroing out for split-K atomics) ----
    prep_kernel<<<NB1 + NB2 + NB3 + NB4, 256>>>(x, grid, w1b, w1s, w2b, w2s,
                                                W1, W2, A1, out);

    // ---- layer 1 GEMM (128x256) + fused layer-2 expansion epilogue ----
    dim3 grid1(D_FF / 256, ntok / 128);
    gemm_mma<2, 4, 4, 8, 1, false, true><<<grid1, 256, smem1>>>(
        A1, W1, nullptr, A2, grid, D_FF, K1P);

    // ---- layer 2 GEMM: 128x128, split-K=2, atomic accumulate ----
    dim3 grid2(D_MODEL / 128, ntok / 128, 2);
    gemm_mma<2, 2, 4, 8, 2, true, false><<<grid2, 128, smem2>>>(
        A2, W2, out, nullptr, nullptr, D_MODEL, K2P);
}

// round 15
// speedup vs baseline: 1.7184x; 1.1962x over previous
#include <cuda_runtime.h>
#include <cuda_fp16.h>
#include <math.h>
#include <stdint.h>

#define D_MODEL 512
#define D_FF    2048
#define GKN     8
#define NTOK    4096

// fp16 K-concat layouts (no hi/lo split needed at fp16 precision):
//  layer1 activations: [bases(4096) | S(512)]    strideK=4608
//  layer1 weights:     [Ws  (4096)  | Wb(512)]
//  layer2 activations: [bases(16384)| S(2048)]   strideK=18432
#define K1P (D_MODEL * GKN + D_MODEL)   // 4608
#define K2P (D_FF * GKN + D_FF)         // 18432

__device__ __half g_A1[(size_t)NTOK * K1P];
__device__ __half g_A2[(size_t)NTOK * K2P];
__device__ __half g_W1[(size_t)D_FF * K1P];
__device__ __half g_W2[(size_t)D_MODEL * K2P];

// ---------------------------------------------------------------------------
// PTX helpers (arch-agnostic on .target sm_103)
// ---------------------------------------------------------------------------
__device__ __forceinline__ uint32_t cvta_smem(const void* p) {
    uint32_t a;
    asm("{ .reg .u64 t; cvta.to.shared.u64 t, %1; cvt.u32.u64 %0, t; }" : "=r"(a) : "l"(p));
    return a;
}
__device__ __forceinline__ void cp16(uint32_t s, const void* g) {
    asm volatile("cp.async.cg.shared.global [%0], [%1], 16;" :: "r"(s), "l"(g));
}
__device__ __forceinline__ void cp_commit() {
    asm volatile("cp.async.commit_group;" ::: "memory");
}
template <int N>
__device__ __forceinline__ void cp_wait() {
    asm volatile("cp.async.wait_group %0;" :: "n"(N) : "memory");
}
__device__ __forceinline__ void ldmx4(uint32_t* r, uint32_t a) {
    asm volatile("ldmatrix.sync.aligned.m8n8.x4.shared.b16 {%0,%1,%2,%3}, [%4];"
                 : "=r"(r[0]), "=r"(r[1]), "=r"(r[2]), "=r"(r[3]) : "r"(a));
}
__device__ __forceinline__ void mma16816(float* d, const uint32_t* a, uint32_t b0, uint32_t b1) {
    asm volatile(
        "mma.sync.aligned.m16n8k16.row.col.f32.f16.f16.f32 "
        "{%0,%1,%2,%3}, {%4,%5,%6,%7}, {%8,%9}, {%0,%1,%2,%3};"
        : "+f"(d[0]), "+f"(d[1]), "+f"(d[2]), "+f"(d[3])
        : "r"(a[0]), "r"(a[1]), "r"(a[2]), "r"(a[3]), "r"(b0), "r"(b1));
}

// ---------------------------------------------------------------------------
// Closed-form uniform cubic B-spline expansion (cardinal N3 translates).
// ---------------------------------------------------------------------------
__device__ __forceinline__ void expand_one(float v, float t0, float ih,
                                           __half& s16, uint4& pk) {
    float s = v * __fdividef(1.0f, 1.0f + __expf(-v));
    s16 = __float2half_rn(s);

    float u = (v - t0) * ih;
    float jf = floorf(u);
    int j0 = (int)jf;
    float w = u - jf;
    float w2 = w * w, w3 = w2 * w;
    const float k6 = 1.0f / 6.0f;
    float c3 = w3 * k6;
    float c2 = k6 * (1.0f + 3.0f * w + 3.0f * w2 - 3.0f * w3);
    float c1 = k6 * (4.0f - 6.0f * w2 + 3.0f * w3);
    float c0 = k6 * (1.0f - 3.0f * w + 3.0f * w2 - w3);

    float bq[8];
#pragma unroll
    for (int q = 0; q < 8; q++) {
        int d = j0 - q;
        float val = 0.0f;
        val = (d == 0) ? c3 : val;
        val = (d == 1) ? c2 : val;
        val = (d == 2) ? c1 : val;
        val = (d == 3) ? c0 : val;
        bq[q] = val;
    }

    __half2 p0 = __floats2half2_rn(bq[0], bq[1]);
    __half2 p1 = __floats2half2_rn(bq[2], bq[3]);
    __half2 p2 = __floats2half2_rn(bq[4], bq[5]);
    __half2 p3 = __floats2half2_rn(bq[6], bq[7]);
    pk.x = *(uint32_t*)&p0; pk.y = *(uint32_t*)&p1;
    pk.z = *(uint32_t*)&p2; pk.w = *(uint32_t*)&p3;
}

// ---------------------------------------------------------------------------
// Per-element job bodies (prep)
// ---------------------------------------------------------------------------
__device__ __forceinline__ void do_expand(const float* __restrict__ x,
                                          float t0, float ih,
                                          __half* __restrict__ pA,
                                          int idx, int in_log2, int strideK) {
    const int IN = 1 << in_log2;
    const int row = idx >> in_log2;
    const int i = idx & (IN - 1);

    __half s16;
    uint4 pk;
    expand_one(x[idx], t0, ih, s16, pk);

    __half* rowp = pA + (size_t)row * strideK;
    *(uint4*)(rowp + i * 8) = pk;
    rowp[IN * 8 + i] = s16;
}

__device__ __forceinline__ void do_pack_w(const float* __restrict__ wb,
                                          const float* __restrict__ ws,
                                          __half* __restrict__ pW,
                                          int idx, int in_log2, int strideK) {
    const int IN = 1 << in_log2;
    const int o = idx >> in_log2;
    const int i = idx & (IN - 1);

    float4 s0 = ((const float4*)ws)[idx * 2];
    float4 s1 = ((const float4*)ws)[idx * 2 + 1];
    __half2 p0 = __floats2half2_rn(s0.x, s0.y);
    __half2 p1 = __floats2half2_rn(s0.z, s0.w);
    __half2 p2 = __floats2half2_rn(s1.x, s1.y);
    __half2 p3 = __floats2half2_rn(s1.z, s1.w);
    uint4 pk;
    pk.x = *(uint32_t*)&p0; pk.y = *(uint32_t*)&p1;
    pk.z = *(uint32_t*)&p2; pk.w = *(uint32_t*)&p3;

    __half* rowp = pW + (size_t)o * strideK;
    *(uint4*)(rowp + i * 8) = pk;
    rowp[IN * 8 + i] = __float2half_rn(wb[idx]);
}

// ---------------------------------------------------------------------------
// Fused preprocessing: pack W1, pack W2, expand layer-1 input, zero out.
// ---------------------------------------------------------------------------
#define NB1 (D_FF * D_MODEL / 256)           // 4096
#define NB2 (D_MODEL * D_FF / 256)           // 4096
#define NB3 (NTOK * D_MODEL / 256)           // 8192
#define NB4 (NTOK * D_MODEL / 256)           // 8192 (zero out)

__global__ void __launch_bounds__(256)
prep_kernel(const float* __restrict__ x, const float* __restrict__ grid,
            const float* __restrict__ w1b, const float* __restrict__ w1s,
            const float* __restrict__ w2b, const float* __restrict__ w2s,
            __half* __restrict__ W1, __half* __restrict__ W2,
            __half* __restrict__ A1, float* __restrict__ outz) {
    const int b = blockIdx.x;
    if (b < NB1) {
        int idx = b * 256 + threadIdx.x;
        do_pack_w(w1b, w1s, W1, idx, 9, K1P);
    } else if (b < NB1 + NB2) {
        int idx = (b - NB1) * 256 + threadIdx.x;
        do_pack_w(w2b, w2s, W2, idx, 11, K2P);
    } else if (b < NB1 + NB2 + NB3) {
        int idx = (b - NB1 - NB2) * 256 + threadIdx.x;
        const float t0 = __ldg(grid);
        const float ih = __fdividef(1.0f, __ldg(grid + 1) - t0);
        do_expand(x, t0, ih, A1, idx, 9, K1P);
    } else {
        int idx = (b - NB1 - NB2 - NB3) * 256 + threadIdx.x;
        outz[idx] = 0.0f;
    }
}

// ---------------------------------------------------------------------------
// fp16 mma.sync GEMM: C(M,Nout) (+)= A(M,K) * B(Nout,K)^T, fp32 accumulate.
// Warp grid WR x WC, warp tile (MI*16) x (NI*8). BK=64, 3-stage cp.async,
// one __syncthreads per K-iter, fragment double-buffering.
// SPLITK: blockIdx.z selects K-half; atomicAdd epilogue (C pre-zeroed).
// KAN: fused layer-2 expansion epilogue — stage acc (=h) in SMEM, then one
//      WARP PER ROW / lanes across columns -> fully coalesced A2 stores.
// ---------------------------------------------------------------------------
#define BKK 64
#define STAGES 3
#define LDT 72
#define HS 260    // fp32 staging stride

template <int WR, int WC, int MI, int NI, int OCC, bool SPLITK, bool KAN>
__global__ void __launch_bounds__(WR * WC * 32, OCC)
gemm_mma(const __half* __restrict__ A, const __half* __restrict__ B,
         float* __restrict__ C, __half* __restrict__ A2,
         const float* __restrict__ gridk, int Nout, int K) {
    constexpr int THREADS = WR * WC * 32;
    constexpr int NWARP = WR * WC;
    constexpr int BM_ = WR * MI * 16;
    constexpr int BN_ = WC * NI * 8;
    constexpr int TILE_A = BM_ * LDT;
    constexpr int TILE_B = BN_ * LDT;
    constexpr int RP = THREADS / 8;
    extern __shared__ __half sm[];
    const uint32_t sm_base = cvta_smem(sm);

    const int tid = threadIdx.x;
    const int lane = tid & 31;
    const int wid = tid >> 5;
    const int wm = wid / WC;
    const int wn = wid % WC;
    const int m0 = blockIdx.y * BM_;
    const int n0 = blockIdx.x * BN_;

    const int kseg = SPLITK ? (K >> 1) : K;
    const size_t koff0 = SPLITK ? (size_t)blockIdx.z * kseg : 0;

    const __half* Ag = A + (size_t)m0 * K + koff0;
    const __half* Bg = B + (size_t)n0 * K + koff0;

    const int lrow = tid >> 3;
    const int lcol = (tid & 7) * 8;

    const int nk = kseg / BKK;

    auto stage_load = [&](int ks) {
        const int buf = ks % STAGES;
        const size_t koff = (size_t)ks * BKK + lcol;
        const uint32_t abase = sm_base + (uint32_t)(buf * (TILE_A + TILE_B)) * 2;
        const uint32_t bbase = abase + (uint32_t)TILE_A * 2;
#pragma unroll
        for (int r = 0; r < BM_; r += RP)
            cp16(abase + (uint32_t)((lrow + r) * LDT + lcol) * 2,
                 Ag + (size_t)(lrow + r) * K + koff);
#pragma unroll
        for (int r = 0; r < BN_; r += RP)
            cp16(bbase + (uint32_t)((lrow + r) * LDT + lcol) * 2,
                 Bg + (size_t)(lrow + r) * K + koff);
        cp_commit();
    };

    float acc[MI][NI][4];
#pragma unroll
    for (int i = 0; i < MI; i++)
#pragma unroll
        for (int j = 0; j < NI; j++)
#pragma unroll
            for (int e = 0; e < 4; e++) acc[i][j][e] = 0.0f;

    const int lm_row = lane & 15;
    const int lm_koff = (lane >> 4) * 8;

    uint32_t afr[2][MI][4];
    uint32_t bfr[2][NI / 2][4];

    stage_load(0);
    stage_load(1);

    for (int ks = 0; ks < nk; ks++) {
        if (ks + 1 < nk) cp_wait<1>(); else cp_wait<0>();
        __syncthreads();
        if (ks + 2 < nk) stage_load(ks + 2);

        const int buf = ks % STAGES;
        const uint32_t abase = sm_base + (uint32_t)(buf * (TILE_A + TILE_B)) * 2 +
                               (uint32_t)((wm * MI * 16 + lm_row) * LDT + lm_koff) * 2;
        const uint32_t bbase = sm_base + (uint32_t)(buf * (TILE_A + TILE_B) + TILE_A) * 2 +
                               (uint32_t)((wn * NI * 8 + lm_row) * LDT + lm_koff) * 2;

#pragma unroll
        for (int mi = 0; mi < MI; mi++)
            ldmx4(afr[0][mi], abase + (uint32_t)(mi * 16 * LDT) * 2);
#pragma unroll
        for (int g = 0; g < NI / 2; g++)
            ldmx4(bfr[0][g], bbase + (uint32_t)(g * 16 * LDT) * 2);

#pragma unroll
        for (int kf = 0; kf < 4; kf++) {
            const int cur = kf & 1, nxt = cur ^ 1;
            if (kf < 3) {
                const uint32_t ka = abase + (uint32_t)((kf + 1) * 16) * 2;
                const uint32_t kb = bbase + (uint32_t)((kf + 1) * 16) * 2;
#pragma unroll
                for (int mi = 0; mi < MI; mi++)
                    ldmx4(afr[nxt][mi], ka + (uint32_t)(mi * 16 * LDT) * 2);
#pragma unroll
                for (int g = 0; g < NI / 2; g++)
                    ldmx4(bfr[nxt][g], kb + (uint32_t)(g * 16 * LDT) * 2);
            }
#pragma unroll
            for (int mi = 0; mi < MI; mi++)
#pragma unroll
                for (int ni = 0; ni < NI; ni++) {
                    const int g = ni >> 1, o = ni & 1;
                    mma16816(acc[mi][ni], afr[cur][mi], bfr[cur][g][o], bfr[cur][g][o + 2]);
                }
        }
    }

    const int erow = lane >> 2;
    const int ecol = (lane & 3) * 2;

    if (KAN) {
        // --- stage acc (=h) to SMEM, then coalesced fused expansion ---
        __syncthreads();
        float* hs = reinterpret_cast<float*>(sm);
#pragma unroll
        for (int mi = 0; mi < MI; mi++)
#pragma unroll
            for (int ni = 0; ni < NI; ni++) {
                const int r = wm * MI * 16 + mi * 16 + erow;
                const int c = wn * NI * 8 + ni * 8 + ecol;
                hs[r * HS + c]           = acc[mi][ni][0];
                hs[r * HS + c + 1]       = acc[mi][ni][1];
                hs[(r + 8) * HS + c]     = acc[mi][ni][2];
                hs[(r + 8) * HS + c + 1] = acc[mi][ni][3];
            }
        __syncthreads();

        const float t0 = __ldg(gridk);
        const float ih = __fdividef(1.0f, __ldg(gridk + 1) - t0);
        const int off = D_FF * 8;
        for (int r = wid; r < BM_; r += NWARP) {
            __half* rowp = A2 + (size_t)(m0 + r) * K2P;
#pragma unroll
            for (int c0 = 0; c0 < BN_; c0 += 32) {
                float v = hs[r * HS + c0 + lane];
                __half s16;
                uint4 pk;
                expand_one(v, t0, ih, s16, pk);
                const int gc = n0 + c0 + lane;
                *(uint4*)(rowp + gc * 8) = pk;    // lanes -> consecutive 16B
                rowp[off + gc] = s16;
            }
        }
    } else {
#pragma unroll
        for (int mi = 0; mi < MI; mi++) {
#pragma unroll
            for (int ni = 0; ni < NI; ni++) {
                const int row = m0 + wm * MI * 16 + mi * 16 + erow;
                const int col = n0 + wn * NI * 8 + ni * 8 + ecol;
                float* p0 = C + (size_t)row * Nout + col;
                float* p1 = C + (size_t)(row + 8) * Nout + col;
                if (SPLITK) {
                    atomicAdd(p0,     acc[mi][ni][0]);
                    atomicAdd(p0 + 1, acc[mi][ni][1]);
                    atomicAdd(p1,     acc[mi][ni][2]);
                    atomicAdd(p1 + 1, acc[mi][ni][3]);
                } else {
                    *(float2*)p0 = make_float2(acc[mi][ni][0], acc[mi][ni][1]);
                    *(float2*)p1 = make_float2(acc[mi][ni][2], acc[mi][ni][3]);
                }
            }
        }
    }
}

// ---------------------------------------------------------------------------
// Launch
// ---------------------------------------------------------------------------
extern "C" void kernel_launch(void* const* d_in, const int* in_sizes, int n_in,
                              void* d_out, int out_size) {
    const float* x    = (const float*)d_in[0];
    const float* grid = (const float*)d_in[1];
    const float* w1b  = (const float*)d_in[2];
    const float* w1s  = (const float*)d_in[3];
    const float* w2b  = (const float*)d_in[4];
    const float* w2s  = (const float*)d_in[5];
    float* out = (float*)d_out;

    const int ntok = in_sizes[0] / D_MODEL;  // 4096

    __half *A1, *A2, *W1, *W2;
    cudaGetSymbolAddress((void**)&A1, g_A1);
    cudaGetSymbolAddress((void**)&A2, g_A2);
    cudaGetSymbolAddress((void**)&W1, g_W1);
    cudaGetSymbolAddress((void**)&W2, g_W2);

    // gemm1: 8 warps (2x4), CTA 128x256, OCC=1, fused KAN epilogue.
    // gemm2: 4 warps (2x2), CTA 128x128, OCC=2, split-K=2, atomics.
    const int smem1 = STAGES * (128 + 256) * LDT * 2;  // 165888
    const int smem2 = STAGES * (128 + 128) * LDT * 2;  // 110592
    cudaFuncSetAttribute((const void*)gemm_mma<2, 4, 4, 8, 1, false, true>,
                         cudaFuncAttributeMaxDynamicSharedMemorySize, smem1);
    cudaFuncSetAttribute((const void*)gemm_mma<2, 2, 4, 8, 2, true, false>,
                         cudaFuncAttributeMaxDynamicSharedMemorySize, smem2);

    // ---- fused preprocessing (incl. zeroing out for split-K atomics) ----
    prep_kernel<<<NB1 + NB2 + NB3 + NB4, 256>>>(x, grid, w1b, w1s, w2b, w2s,
                                                W1, W2, A1, out);

    // ---- layer 1 GEMM (128x256, K=4608) + fused layer-2 expansion ----
    dim3 grid1(D_FF / 256, ntok / 128);
    gemm_mma<2, 4, 4, 8, 1, false, true><<<grid1, 256, smem1>>>(
        A1, W1, nullptr, A2, grid, D_FF, K1P);

    // ---- layer 2 GEMM: 128x128, K=18432, split-K=2, atomic accumulate ----
    dim3 grid2(D_MODEL / 128, ntok / 128, 2);
    gemm_mma<2, 2, 4, 8, 2, true, false><<<grid2, 128, smem2>>>(
        A2, W2, out, nullptr, nullptr, D_MODEL, K2P);
}

// round 16
// speedup vs baseline: 1.7447x; 1.0153x over previous
#include <cuda_runtime.h>
#include <cuda_fp16.h>
#include <math.h>
#include <stdint.h>

#define D_MODEL 512
#define D_FF    2048
#define GKN     8
#define NTOK    4096

// fp16 K-concat layouts (no hi/lo split needed at fp16 precision):
//  layer1 activations: [bases(4096) | S(512)]    strideK=4608
//  layer1 weights:     [Ws  (4096)  | Wb(512)]
//  layer2 activations: [bases(16384)| S(2048)]   strideK=18432
#define K1P (D_MODEL * GKN + D_MODEL)   // 4608
#define K2P (D_FF * GKN + D_FF)         // 18432

__device__ __half g_A1[(size_t)NTOK * K1P];
__device__ __half g_A2[(size_t)NTOK * K2P];
__device__ __half g_W1[(size_t)D_FF * K1P];
__device__ __half g_W2[(size_t)D_MODEL * K2P];

// ---------------------------------------------------------------------------
// PTX helpers (arch-agnostic on .target sm_103)
// ---------------------------------------------------------------------------
__device__ __forceinline__ uint32_t cvta_smem(const void* p) {
    uint32_t a;
    asm("{ .reg .u64 t; cvta.to.shared.u64 t, %1; cvt.u32.u64 %0, t; }" : "=r"(a) : "l"(p));
    return a;
}
__device__ __forceinline__ void cp16(uint32_t s, const void* g) {
    asm volatile("cp.async.cg.shared.global [%0], [%1], 16;" :: "r"(s), "l"(g));
}
__device__ __forceinline__ void cp_commit() {
    asm volatile("cp.async.commit_group;" ::: "memory");
}
template <int N>
__device__ __forceinline__ void cp_wait() {
    asm volatile("cp.async.wait_group %0;" :: "n"(N) : "memory");
}
__device__ __forceinline__ void ldmx4(uint32_t* r, uint32_t a) {
    asm volatile("ldmatrix.sync.aligned.m8n8.x4.shared.b16 {%0,%1,%2,%3}, [%4];"
                 : "=r"(r[0]), "=r"(r[1]), "=r"(r[2]), "=r"(r[3]) : "r"(a));
}
__device__ __forceinline__ void mma16816(float* d, const uint32_t* a, uint32_t b0, uint32_t b1) {
    asm volatile(
        "mma.sync.aligned.m16n8k16.row.col.f32.f16.f16.f32 "
        "{%0,%1,%2,%3}, {%4,%5,%6,%7}, {%8,%9}, {%0,%1,%2,%3};"
        : "+f"(d[0]), "+f"(d[1]), "+f"(d[2]), "+f"(d[3])
        : "r"(a[0]), "r"(a[1]), "r"(a[2]), "r"(a[3]), "r"(b0), "r"(b1));
}

// ---------------------------------------------------------------------------
// Closed-form uniform cubic B-spline expansion (cardinal N3 translates).
// ---------------------------------------------------------------------------
__device__ __forceinline__ void expand_one(float v, float t0, float ih,
                                           __half& s16, uint4& pk) {
    float s = v * __fdividef(1.0f, 1.0f + __expf(-v));
    s16 = __float2half_rn(s);

    float u = (v - t0) * ih;
    float jf = floorf(u);
    int j0 = (int)jf;
    float w = u - jf;
    float w2 = w * w, w3 = w2 * w;
    const float k6 = 1.0f / 6.0f;
    float c3 = w3 * k6;
    float c2 = k6 * (1.0f + 3.0f * w + 3.0f * w2 - 3.0f * w3);
    float c1 = k6 * (4.0f - 6.0f * w2 + 3.0f * w3);
    float c0 = k6 * (1.0f - 3.0f * w + 3.0f * w2 - w3);

    float bq[8];
#pragma unroll
    for (int q = 0; q < 8; q++) {
        int d = j0 - q;
        float val = 0.0f;
        val = (d == 0) ? c3 : val;
        val = (d == 1) ? c2 : val;
        val = (d == 2) ? c1 : val;
        val = (d == 3) ? c0 : val;
        bq[q] = val;
    }

    __half2 p0 = __floats2half2_rn(bq[0], bq[1]);
    __half2 p1 = __floats2half2_rn(bq[2], bq[3]);
    __half2 p2 = __floats2half2_rn(bq[4], bq[5]);
    __half2 p3 = __floats2half2_rn(bq[6], bq[7]);
    pk.x = *(uint32_t*)&p0; pk.y = *(uint32_t*)&p1;
    pk.z = *(uint32_t*)&p2; pk.w = *(uint32_t*)&p3;
}

// ---------------------------------------------------------------------------
// Per-element job bodies (prep / aux)
// ---------------------------------------------------------------------------
__device__ __forceinline__ void do_expand(const float* __restrict__ x,
                                          float t0, float ih,
                                          __half* __restrict__ pA,
                                          int idx, int in_log2, int strideK) {
    const int IN = 1 << in_log2;
    const int row = idx >> in_log2;
    const int i = idx & (IN - 1);

    __half s16;
    uint4 pk;
    expand_one(x[idx], t0, ih, s16, pk);

    __half* rowp = pA + (size_t)row * strideK;
    *(uint4*)(rowp + i * 8) = pk;
    rowp[IN * 8 + i] = s16;
}

__device__ __forceinline__ void do_pack_w(const float* __restrict__ wb,
                                          const float* __restrict__ ws,
                                          __half* __restrict__ pW,
                                          int idx, int in_log2, int strideK) {
    const int IN = 1 << in_log2;
    const int o = idx >> in_log2;
    const int i = idx & (IN - 1);

    float4 s0 = ((const float4*)ws)[idx * 2];
    float4 s1 = ((const float4*)ws)[idx * 2 + 1];
    __half2 p0 = __floats2half2_rn(s0.x, s0.y);
    __half2 p1 = __floats2half2_rn(s0.z, s0.w);
    __half2 p2 = __floats2half2_rn(s1.x, s1.y);
    __half2 p3 = __floats2half2_rn(s1.z, s1.w);
    uint4 pk;
    pk.x = *(uint32_t*)&p0; pk.y = *(uint32_t*)&p1;
    pk.z = *(uint32_t*)&p2; pk.w = *(uint32_t*)&p3;

    __half* rowp = pW + (size_t)o * strideK;
    *(uint4*)(rowp + i * 8) = pk;
    rowp[IN * 8 + i] = __float2half_rn(wb[idx]);
}

// ---------------------------------------------------------------------------
// Preprocessing needed BEFORE gemm1: pack W1, expand layer-1 input.
// (W2 pack and out-zeroing are aux jobs inside gemm1's grid.)
// ---------------------------------------------------------------------------
#define NB1 (D_FF * D_MODEL / 256)           // 4096
#define NB3 (NTOK * D_MODEL / 256)           // 8192

__global__ void __launch_bounds__(256)
prep_kernel(const float* __restrict__ x, const float* __restrict__ grid,
            const float* __restrict__ w1b, const float* __restrict__ w1s,
            __half* __restrict__ W1, __half* __restrict__ A1) {
    const int b = blockIdx.x;
    if (b < NB1) {
        int idx = b * 256 + threadIdx.x;
        do_pack_w(w1b, w1s, W1, idx, 9, K1P);
    } else {
        int idx = (b - NB1) * 256 + threadIdx.x;
        const float t0 = __ldg(grid);
        const float ih = __fdividef(1.0f, __ldg(grid + 1) - t0);
        do_expand(x, t0, ih, A1, idx, 9, K1P);
    }
}

// ---------------------------------------------------------------------------
// fp16 mma.sync GEMM: C(M,Nout) (+)= A(M,K) * B(Nout,K)^T, fp32 accumulate.
// Warp grid WR x WC, warp tile (MI*16) x (NI*8). BK=64, 3-stage cp.async,
// one __syncthreads per K-iter, fragment double-buffering.
// SPLITK: blockIdx.z selects K-half; atomicAdd epilogue (C pre-zeroed).
// KAN: fused layer-2 expansion epilogue (coalesced A2 stores), plus
//      AUX CTAs (blockIdx.y >= gy_main) that pack W2 / zero out on the
//      idle SMs of gemm1's ragged second wave.
// ---------------------------------------------------------------------------
#define BKK 64
#define STAGES 3
#define LDT 72
#define HS 260    // fp32 staging stride
#define AUXY 8    // aux rows appended to gemm1 grid (8 x gridDim.x CTAs)

template <int WR, int WC, int MI, int NI, int OCC, bool SPLITK, bool KAN>
__global__ void __launch_bounds__(WR * WC * 32, OCC)
gemm_mma(const __half* __restrict__ A, const __half* __restrict__ B,
         float* __restrict__ C, __half* __restrict__ A2,
         const float* __restrict__ gridk,
         const float* __restrict__ w2b, const float* __restrict__ w2s,
         __half* __restrict__ W2p, float* __restrict__ outz,
         int gy_main, int Nout, int K) {
    constexpr int THREADS = WR * WC * 32;
    constexpr int NWARP = WR * WC;
    constexpr int BM_ = WR * MI * 16;
    constexpr int BN_ = WC * NI * 8;
    constexpr int TILE_A = BM_ * LDT;
    constexpr int TILE_B = BN_ * LDT;
    constexpr int RP = THREADS / 8;

    if (KAN && (int)blockIdx.y >= gy_main) {
        // ---- aux job: pack W2 + zero out (runs on idle wave-2 SMs) ----
        const int aid = ((int)blockIdx.y - gy_main) * gridDim.x + blockIdx.x;
        const int nthr = AUXY * 8 * THREADS;      // total aux threads
        const int gtid = aid * THREADS + threadIdx.x;
        for (int idx = gtid; idx < D_MODEL * D_FF; idx += nthr)
            do_pack_w(w2b, w2s, W2p, idx, 11, K2P);
        const float4 z = make_float4(0.f, 0.f, 0.f, 0.f);
        for (int i = gtid; i < NTOK * D_MODEL / 4; i += nthr)
            ((float4*)outz)[i] = z;
        return;
    }

    extern __shared__ __half sm[];
    const uint32_t sm_base = cvta_smem(sm);

    const int tid = threadIdx.x;
    const int lane = tid & 31;
    const int wid = tid >> 5;
    const int wm = wid / WC;
    const int wn = wid % WC;
    const int m0 = blockIdx.y * BM_;
    const int n0 = blockIdx.x * BN_;

    const int kseg = SPLITK ? (K >> 1) : K;
    const size_t koff0 = SPLITK ? (size_t)blockIdx.z * kseg : 0;

    const __half* Ag = A + (size_t)m0 * K + koff0;
    const __half* Bg = B + (size_t)n0 * K + koff0;

    const int lrow = tid >> 3;
    const int lcol = (tid & 7) * 8;

    const int nk = kseg / BKK;

    auto stage_load = [&](int ks) {
        const int buf = ks % STAGES;
        const size_t koff = (size_t)ks * BKK + lcol;
        const uint32_t abase = sm_base + (uint32_t)(buf * (TILE_A + TILE_B)) * 2;
        const uint32_t bbase = abase + (uint32_t)TILE_A * 2;
#pragma unroll
        for (int r = 0; r < BM_; r += RP)
            cp16(abase + (uint32_t)((lrow + r) * LDT + lcol) * 2,
                 Ag + (size_t)(lrow + r) * K + koff);
#pragma unroll
        for (int r = 0; r < BN_; r += RP)
            cp16(bbase + (uint32_t)((lrow + r) * LDT + lcol) * 2,
                 Bg + (size_t)(lrow + r) * K + koff);
        cp_commit();
    };

    float acc[MI][NI][4];
#pragma unroll
    for (int i = 0; i < MI; i++)
#pragma unroll
        for (int j = 0; j < NI; j++)
#pragma unroll
            for (int e = 0; e < 4; e++) acc[i][j][e] = 0.0f;

    const int lm_row = lane & 15;
    const int lm_koff = (lane >> 4) * 8;

    uint32_t afr[2][MI][4];
    uint32_t bfr[2][NI / 2][4];

    stage_load(0);
    stage_load(1);

    for (int ks = 0; ks < nk; ks++) {
        if (ks + 1 < nk) cp_wait<1>(); else cp_wait<0>();
        __syncthreads();
        if (ks + 2 < nk) stage_load(ks + 2);

        const int buf = ks % STAGES;
        const uint32_t abase = sm_base + (uint32_t)(buf * (TILE_A + TILE_B)) * 2 +
                               (uint32_t)((wm * MI * 16 + lm_row) * LDT + lm_koff) * 2;
        const uint32_t bbase = sm_base + (uint32_t)(buf * (TILE_A + TILE_B) + TILE_A) * 2 +
                               (uint32_t)((wn * NI * 8 + lm_row) * LDT + lm_koff) * 2;

#pragma unroll
        for (int mi = 0; mi < MI; mi++)
            ldmx4(afr[0][mi], abase + (uint32_t)(mi * 16 * LDT) * 2);
#pragma unroll
        for (int g = 0; g < NI / 2; g++)
            ldmx4(bfr[0][g], bbase + (uint32_t)(g * 16 * LDT) * 2);

#pragma unroll
        for (int kf = 0; kf < 4; kf++) {
            const int cur = kf & 1, nxt = cur ^ 1;
            if (kf < 3) {
                const uint32_t ka = abase + (uint32_t)((kf + 1) * 16) * 2;
                const uint32_t kb = bbase + (uint32_t)((kf + 1) * 16) * 2;
#pragma unroll
                for (int mi = 0; mi < MI; mi++)
                    ldmx4(afr[nxt][mi], ka + (uint32_t)(mi * 16 * LDT) * 2);
#pragma unroll
                for (int g = 0; g < NI / 2; g++)
                    ldmx4(bfr[nxt][g], kb + (uint32_t)(g * 16 * LDT) * 2);
            }
#pragma unroll
            for (int mi = 0; mi < MI; mi++)
#pragma unroll
                for (int ni = 0; ni < NI; ni++) {
                    const int g = ni >> 1, o = ni & 1;
                    mma16816(acc[mi][ni], afr[cur][mi], bfr[cur][g][o], bfr[cur][g][o + 2]);
                }
        }
    }

    const int erow = lane >> 2;
    const int ecol = (lane & 3) * 2;

    if (KAN) {
        // --- stage acc (=h) to SMEM, then coalesced fused expansion ---
        __syncthreads();
        float* hs = reinterpret_cast<float*>(sm);
#pragma unroll
        for (int mi = 0; mi < MI; mi++)
#pragma unroll
            for (int ni = 0; ni < NI; ni++) {
                const int r = wm * MI * 16 + mi * 16 + erow;
                const int c = wn * NI * 8 + ni * 8 + ecol;
                hs[r * HS + c]           = acc[mi][ni][0];
                hs[r * HS + c + 1]       = acc[mi][ni][1];
                hs[(r + 8) * HS + c]     = acc[mi][ni][2];
                hs[(r + 8) * HS + c + 1] = acc[mi][ni][3];
            }
        __syncthreads();

        const float t0 = __ldg(gridk);
        const float ih = __fdividef(1.0f, __ldg(gridk + 1) - t0);
        const int off = D_FF * 8;
        for (int r = wid; r < BM_; r += NWARP) {
            __half* rowp = A2 + (size_t)(m0 + r) * K2P;
#pragma unroll
            for (int c0 = 0; c0 < BN_; c0 += 32) {
                float v = hs[r * HS + c0 + lane];
                __half s16;
                uint4 pk;
                expand_one(v, t0, ih, s16, pk);
                const int gc = n0 + c0 + lane;
                *(uint4*)(rowp + gc * 8) = pk;    // lanes -> consecutive 16B
                rowp[off + gc] = s16;
            }
        }
    } else {
#pragma unroll
        for (int mi = 0; mi < MI; mi++) {
#pragma unroll
            for (int ni = 0; ni < NI; ni++) {
                const int row = m0 + wm * MI * 16 + mi * 16 + erow;
                const int col = n0 + wn * NI * 8 + ni * 8 + ecol;
                float* p0 = C + (size_t)row * Nout + col;
                float* p1 = C + (size_t)(row + 8) * Nout + col;
                if (SPLITK) {
                    atomicAdd(p0,     acc[mi][ni][0]);
                    atomicAdd(p0 + 1, acc[mi][ni][1]);
                    atomicAdd(p1,     acc[mi][ni][2]);
                    atomicAdd(p1 + 1, acc[mi][ni][3]);
                } else {
                    *(float2*)p0 = make_float2(acc[mi][ni][0], acc[mi][ni][1]);
                    *(float2*)p1 = make_float2(acc[mi][ni][2], acc[mi][ni][3]);
                }
            }
        }
    }
}

// ---------------------------------------------------------------------------
// Launch
// ---------------------------------------------------------------------------
extern "C" void kernel_launch(void* const* d_in, const int* in_sizes, int n_in,
                              void* d_out, int out_size) {
    const float* x    = (const float*)d_in[0];
    const float* grid = (const float*)d_in[1];
    const float* w1b  = (const float*)d_in[2];
    const float* w1s  = (const float*)d_in[3];
    const float* w2b  = (const float*)d_in[4];
    const float* w2s  = (const float*)d_in[5];
    float* out = (float*)d_out;

    const int ntok = in_sizes[0] / D_MODEL;  // 4096

    __half *A1, *A2, *W1, *W2;
    cudaGetSymbolAddress((void**)&A1, g_A1);
    cudaGetSymbolAddress((void**)&A2, g_A2);
    cudaGetSymbolAddress((void**)&W1, g_W1);
    cudaGetSymbolAddress((void**)&W2, g_W2);

    // gemm1: 8 warps (2x4), CTA 128x256, OCC=1, fused KAN epilogue + aux CTAs.
    // gemm2: 4 warps (2x2), CTA 128x128, OCC=2, split-K=2, atomics.
    const int smem1 = STAGES * (128 + 256) * LDT * 2;  // 165888
    const int smem2 = STAGES * (128 + 128) * LDT * 2;  // 110592
    cudaFuncSetAttribute((const void*)gemm_mma<2, 4, 4, 8, 1, false, true>,
                         cudaFuncAttributeMaxDynamicSharedMemorySize, smem1);
    cudaFuncSetAttribute((const void*)gemm_mma<2, 2, 4, 8, 2, true, false>,
                         cudaFuncAttributeMaxDynamicSharedMemorySize, smem2);

    // ---- preprocessing needed before gemm1 (W1 pack + expand x) ----
    prep_kernel<<<NB1 + NB3, 256>>>(x, grid, w1b, w1s, W1, A1);

    // ---- layer 1 GEMM (128x256, K=4608) + fused layer-2 expansion,
    //      with aux CTAs (blockIdx.y >= 32) packing W2 + zeroing out ----
    const int gy_main = ntok / 128;   // 32
    dim3 grid1(D_FF / 256, gy_main + AUXY);
    gemm_mma<2, 4, 4, 8, 1, false, true><<<grid1, 256, smem1>>>(
        A1, W1, nullptr, A2, grid, w2b, w2s, W2, out, gy_main, D_FF, K1P);

    // ---- layer 2 GEMM: 128x128, K=18432, split-K=2, atomic accumulate ----
    dim3 grid2(D_MODEL / 128, ntok / 128, 2);
    gemm_mma<2, 2, 4, 8, 2, true, false><<<grid2, 128, smem2>>>(
        A2, W2, out, nullptr, nullptr, nullptr, nullptr, nullptr, nullptr,
        1 << 30, D_MODEL, K2P);
}